// round 14
// baseline (speedup 1.0000x reference)
#include <cuda_runtime.h>

// ParallelBellowsLayers: per-channel 1->16->1 MLP with ReLU, C=40000, B=128, E=16.
// out[b,c] = relu( sum_e relu(x[b,c]*w1[c,e]+b1[c,e]) * w2[c,e] + b2[c] )
// Output (B,2,20000) == (B,C) row-major -> elementwise in x's layout.
// b1[c,:]==0 (this dataset) => sum_e relu(x*w1e)*w2e == x * (x>0 ? s_pos : s_neg).
//
// R13 leak: default persisting-L2 carveout is 25.4 MB. Tagging EVERYTHING
// evict_last (R6-R12) oversubscribed it 41.5MB->24MB and thrashed x out each
// pass. This round fits the carveout: x (20.5MB) + params (0.5MB) evict_last,
// out stores evict_first (streaming, keep out of the carveout), weights on the
// normal class. Structure unchanged from R12 (PDL overlap, 1280-block apply).
// NaN-flag in s_pos routes nonzero-b1 / non-finite channels to an exact
// per-element fallback (never taken on this dataset).

#define NGENES 20000
#define NTECH  2
#define CC     (NGENES * NTECH)   // 40000
#define BB     128
#define EE     16
#define NG     (CC / 4)           // 10000 float4 channel-groups
#define RROWS  4                  // batch rows per thread in apply

// SoA per-channel params (NaN in g_sp[c] => exact-fallback channel)
__device__ float g_sp[CC];
__device__ float g_sn[CC];
__device__ float g_bf[CC];

// ---- cache-policy memory ops ------------------------------------------------
__device__ __forceinline__ unsigned long long mk_keep()    // persist in carveout
{
    unsigned long long pol;
    asm volatile("createpolicy.fractional.L2::evict_last.b64 %0, 1.0;" : "=l"(pol));
    return pol;
}
__device__ __forceinline__ unsigned long long mk_stream()  // evict ASAP
{
    unsigned long long pol;
    asm volatile("createpolicy.fractional.L2::evict_first.b64 %0, 1.0;" : "=l"(pol));
    return pol;
}
__device__ __forceinline__ float4 ldg_pol(const float* p, unsigned long long pol)
{
    float4 v;
    asm volatile("ld.global.nc.L2::cache_hint.v4.f32 {%0,%1,%2,%3}, [%4], %5;"
                 : "=f"(v.x), "=f"(v.y), "=f"(v.z), "=f"(v.w)
                 : "l"(p), "l"(pol));
    return v;
}
__device__ __forceinline__ float ldg_pol1(const float* p, unsigned long long pol)
{
    float v;
    asm volatile("ld.global.nc.L2::cache_hint.f32 %0, [%1], %2;"
                 : "=f"(v) : "l"(p), "l"(pol));
    return v;
}
__device__ __forceinline__ void stg_pol(float* p, float4 v, unsigned long long pol)
{
    asm volatile("st.global.L2::cache_hint.v4.f32 [%0], {%1,%2,%3,%4}, %5;"
                 :: "l"(p), "f"(v.x), "f"(v.y), "f"(v.z), "f"(v.w), "l"(pol)
                 : "memory");
}
// -----------------------------------------------------------------------------

// Precompute: 4 threads per channel, shfl-reduced; signals dependents early.
// Weights stay on the normal L2 class (plain __ldg) -- don't touch the carveout.
__global__ void __launch_bounds__(256)
precompute_kernel(const float* __restrict__ w1,
                  const float* __restrict__ b1,
                  const float* __restrict__ w2,
                  const float* __restrict__ b2)
{
    int t = blockIdx.x * 256 + threadIdx.x;
    int c = t >> 2;
    int part = t & 3;
    if (c >= CC) return;   // exited threads satisfy launch_dependents

    size_t vi = (size_t)c * 4 + part;
    float4 a = __ldg(reinterpret_cast<const float4*>(w1) + vi);
    float4 z = __ldg(reinterpret_cast<const float4*>(b1) + vi);
    float4 w = __ldg(reinterpret_cast<const float4*>(w2) + vi);

    bool ok = (z.x == 0.f) && (z.y == 0.f) && (z.z == 0.f) && (z.w == 0.f);

    float sp = 0.f, sn = 0.f, p;
    p = a.x * w.x; sp += (a.x > 0.f) ? p : 0.f; sn += (a.x < 0.f) ? p : 0.f;
    p = a.y * w.y; sp += (a.y > 0.f) ? p : 0.f; sn += (a.y < 0.f) ? p : 0.f;
    p = a.z * w.z; sp += (a.z > 0.f) ? p : 0.f; sn += (a.z < 0.f) ? p : 0.f;
    p = a.w * w.w; sp += (a.w > 0.f) ? p : 0.f; sn += (a.w < 0.f) ? p : 0.f;

    if (!ok) sp = __int_as_float(0x7fc00000);   // NaN survives the reduction

    sp += __shfl_xor_sync(0xffffffffu, sp, 1);
    sp += __shfl_xor_sync(0xffffffffu, sp, 2);
    sn += __shfl_xor_sync(0xffffffffu, sn, 1);
    sn += __shfl_xor_sync(0xffffffffu, sn, 2);

    if (part == 0) {
        if (!isfinite(sp) || !isfinite(sn)) sp = __int_as_float(0x7fc00000);
        g_sp[c] = sp;
        g_sn[c] = sn;
        g_bf[c] = __ldg(b2 + c);
    }

    asm volatile("griddepcontrol.launch_dependents;");
}

// Exact per-element path for flagged channels (never taken on this dataset).
__device__ __noinline__ float bellows_exact(float xv, int c,
                                            const float* __restrict__ w1,
                                            const float* __restrict__ b1,
                                            const float* __restrict__ w2,
                                            float bias)
{
    float acc = 0.f;
    const float* w1r = w1 + (size_t)c * EE;
    const float* b1r = b1 + (size_t)c * EE;
    const float* w2r = w2 + (size_t)c * EE;
#pragma unroll 4
    for (int e = 0; e < EE; ++e) {
        float h = fmaxf(fmaf(xv, w1r[e], b1r[e]), 0.f);
        acc = fmaf(h, w2r[e], acc);
    }
    return fmaxf(acc + bias, 0.f);
}

__device__ __forceinline__ float bellows_fast(float xv, float sp, float sn, float bias)
{
    float s = (xv > 0.f) ? sp : sn;
    return fmaxf(fmaf(xv, s, bias), 0.f);
}

__global__ void __launch_bounds__(256)
apply_kernel(const float* __restrict__ x,
             const float* __restrict__ w1,
             const float* __restrict__ b1,
             const float* __restrict__ w2,
             float* __restrict__ out)
{
    int g = blockIdx.x * 256 + threadIdx.x;   // group of 4 channels
    if (g >= NG) return;
    int c  = g * 4;
    int b0 = blockIdx.y * RROWS;

    unsigned long long keep   = mk_keep();    // x + params: persist
    unsigned long long stream = mk_stream();  // out: evict first

    const float* xp = x + (size_t)b0 * CC + c;
    float*       op = out + (size_t)b0 * CC + c;

    // x is independent of the precompute kernel: issue these loads BEFORE
    // griddepcontrol.wait so the predecessor's tail hides under them.
    float4 xv0 = ldg_pol(xp, keep);
    float4 xv1 = ldg_pol(xp + (size_t)1 * CC, keep);
    float4 xv2 = ldg_pol(xp + (size_t)2 * CC, keep);
    float4 xv3 = ldg_pol(xp + (size_t)3 * CC, keep);

    asm volatile("griddepcontrol.wait;" ::: "memory");

    float4 sp = ldg_pol(g_sp + c, keep);
    float4 sn = ldg_pol(g_sn + c, keep);
    float4 bf = ldg_pol(g_bf + c, keep);

    bool any_fb = (sp.x != sp.x) || (sp.y != sp.y) || (sp.z != sp.z) || (sp.w != sp.w);

    if (!any_fb) {
        float4 o;
        o.x = bellows_fast(xv0.x, sp.x, sn.x, bf.x);
        o.y = bellows_fast(xv0.y, sp.y, sn.y, bf.y);
        o.z = bellows_fast(xv0.z, sp.z, sn.z, bf.z);
        o.w = bellows_fast(xv0.w, sp.w, sn.w, bf.w);
        stg_pol(op, o, stream);
        o.x = bellows_fast(xv1.x, sp.x, sn.x, bf.x);
        o.y = bellows_fast(xv1.y, sp.y, sn.y, bf.y);
        o.z = bellows_fast(xv1.z, sp.z, sn.z, bf.z);
        o.w = bellows_fast(xv1.w, sp.w, sn.w, bf.w);
        stg_pol(op + (size_t)1 * CC, o, stream);
        o.x = bellows_fast(xv2.x, sp.x, sn.x, bf.x);
        o.y = bellows_fast(xv2.y, sp.y, sn.y, bf.y);
        o.z = bellows_fast(xv2.z, sp.z, sn.z, bf.z);
        o.w = bellows_fast(xv2.w, sp.w, sn.w, bf.w);
        stg_pol(op + (size_t)2 * CC, o, stream);
        o.x = bellows_fast(xv3.x, sp.x, sn.x, bf.x);
        o.y = bellows_fast(xv3.y, sp.y, sn.y, bf.y);
        o.z = bellows_fast(xv3.z, sp.z, sn.z, bf.z);
        o.w = bellows_fast(xv3.w, sp.w, sn.w, bf.w);
        stg_pol(op + (size_t)3 * CC, o, stream);
    } else {
        float4 xs[RROWS] = {xv0, xv1, xv2, xv3};
#pragma unroll
        for (int r = 0; r < RROWS; ++r) {
            float4 xv = xs[r];
            float4 o;
            o.x = (sp.x != sp.x) ? bellows_exact(xv.x, c + 0, w1, b1, w2, bf.x)
                                 : bellows_fast(xv.x, sp.x, sn.x, bf.x);
            o.y = (sp.y != sp.y) ? bellows_exact(xv.y, c + 1, w1, b1, w2, bf.y)
                                 : bellows_fast(xv.y, sp.y, sn.y, bf.y);
            o.z = (sp.z != sp.z) ? bellows_exact(xv.z, c + 2, w1, b1, w2, bf.z)
                                 : bellows_fast(xv.z, sp.z, sn.z, bf.z);
            o.w = (sp.w != sp.w) ? bellows_exact(xv.w, c + 3, w1, b1, w2, bf.w)
                                 : bellows_fast(xv.w, sp.w, sn.w, bf.w);
            stg_pol(op + (size_t)r * CC, o, stream);
        }
    }
}

extern "C" void kernel_launch(void* const* d_in, const int* in_sizes, int n_in,
                              void* d_out, int out_size)
{
    const float* x  = (const float*)d_in[0];   // (128, 40000)
    const float* w1 = (const float*)d_in[1];   // (40000, 16)
    const float* b1 = (const float*)d_in[2];   // (40000, 16)
    const float* w2 = (const float*)d_in[3];   // (40000, 16)
    const float* b2 = (const float*)d_in[4];   // (40000,)
    float* out = (float*)d_out;                // (128, 2, 20000) == (128, 40000)

    precompute_kernel<<<(CC * 4 + 255) / 256, 256>>>(w1, b1, w2, b2);

    // apply: Programmatic Stream Serialization so it begins while precompute
    // drains; griddepcontrol.wait provides the param-visibility ordering.
    cudaLaunchConfig_t cfg = {};
    cfg.gridDim  = dim3((NG + 255) / 256, BB / RROWS);   // (40, 32) = 1280 blocks
    cfg.blockDim = dim3(256, 1, 1);
    cfg.dynamicSmemBytes = 0;
    cfg.stream = 0;   // same (capture) stream as the precompute launch

    cudaLaunchAttribute attrs[1];
    attrs[0].id = cudaLaunchAttributeProgrammaticStreamSerialization;
    attrs[0].val.programmaticStreamSerializationAllowed = 1;
    cfg.attrs = attrs;
    cfg.numAttrs = 1;

    cudaLaunchKernelEx(&cfg, apply_kernel, x, w1, b1, w2, out);
}

// round 15
// speedup vs baseline: 1.0030x; 1.0030x over previous
#include <cuda_runtime.h>

// ParallelBellowsLayers: per-channel 1->16->1 MLP with ReLU, C=40000, B=128, E=16.
// out[b,c] = relu( sum_e relu(x[b,c]*w1[c,e]+b1[c,e]) * w2[c,e] + b2[c] )
// Output (B,2,20000) == (B,C) row-major -> elementwise in x's layout.
// b1[c,:]==0 (this dataset) => sum_e relu(x*w1e)*w2e == x * (x>0 ? s_pos : s_neg).
//
// R15 theory: steady-state graph replay is a 50/50 DRAM read/write duplex
// (28.3MB reads + 20.5MB prior-replay writebacks) -- the worst case for HBM
// bus efficiency, and why every read mechanism pegs at ~2.25 TB/s. Fix: pin
// OUT (20.5MB < 24.2MB carveout) as evict_last so each replay's stores are
// L2 write-hits on resident dirty lines and writebacks never occur; x streams
// evict_first; weights normal class. Structure = R12 (PDL overlap, 1280-block
// apply, loads issued before griddepcontrol.wait).
// NaN-flag in s_pos routes nonzero-b1 / non-finite channels to an exact
// per-element fallback (never taken on this dataset).

#define NGENES 20000
#define NTECH  2
#define CC     (NGENES * NTECH)   // 40000
#define BB     128
#define EE     16
#define NG     (CC / 4)           // 10000 float4 channel-groups
#define RROWS  4                  // batch rows per thread in apply

// SoA per-channel params (NaN in g_sp[c] => exact-fallback channel)
__device__ float g_sp[CC];
__device__ float g_sn[CC];
__device__ float g_bf[CC];

// ---- cache-policy memory ops ------------------------------------------------
__device__ __forceinline__ unsigned long long mk_keep()    // persist in carveout
{
    unsigned long long pol;
    asm volatile("createpolicy.fractional.L2::evict_last.b64 %0, 1.0;" : "=l"(pol));
    return pol;
}
__device__ __forceinline__ unsigned long long mk_stream()  // evict ASAP
{
    unsigned long long pol;
    asm volatile("createpolicy.fractional.L2::evict_first.b64 %0, 1.0;" : "=l"(pol));
    return pol;
}
__device__ __forceinline__ float4 ldg_pol(const float* p, unsigned long long pol)
{
    float4 v;
    asm volatile("ld.global.nc.L2::cache_hint.v4.f32 {%0,%1,%2,%3}, [%4], %5;"
                 : "=f"(v.x), "=f"(v.y), "=f"(v.z), "=f"(v.w)
                 : "l"(p), "l"(pol));
    return v;
}
__device__ __forceinline__ void stg_pol(float* p, float4 v, unsigned long long pol)
{
    asm volatile("st.global.L2::cache_hint.v4.f32 [%0], {%1,%2,%3,%4}, %5;"
                 :: "l"(p), "f"(v.x), "f"(v.y), "f"(v.z), "f"(v.w), "l"(pol)
                 : "memory");
}
// -----------------------------------------------------------------------------

// Precompute: 4 threads per channel, shfl-reduced; signals dependents early.
// Weights stay on the normal L2 class -- keep the carveout for out+params.
__global__ void __launch_bounds__(256)
precompute_kernel(const float* __restrict__ w1,
                  const float* __restrict__ b1,
                  const float* __restrict__ w2,
                  const float* __restrict__ b2)
{
    int t = blockIdx.x * 256 + threadIdx.x;
    int c = t >> 2;
    int part = t & 3;
    if (c >= CC) return;   // exited threads satisfy launch_dependents

    size_t vi = (size_t)c * 4 + part;
    float4 a = __ldg(reinterpret_cast<const float4*>(w1) + vi);
    float4 z = __ldg(reinterpret_cast<const float4*>(b1) + vi);
    float4 w = __ldg(reinterpret_cast<const float4*>(w2) + vi);

    bool ok = (z.x == 0.f) && (z.y == 0.f) && (z.z == 0.f) && (z.w == 0.f);

    float sp = 0.f, sn = 0.f, p;
    p = a.x * w.x; sp += (a.x > 0.f) ? p : 0.f; sn += (a.x < 0.f) ? p : 0.f;
    p = a.y * w.y; sp += (a.y > 0.f) ? p : 0.f; sn += (a.y < 0.f) ? p : 0.f;
    p = a.z * w.z; sp += (a.z > 0.f) ? p : 0.f; sn += (a.z < 0.f) ? p : 0.f;
    p = a.w * w.w; sp += (a.w > 0.f) ? p : 0.f; sn += (a.w < 0.f) ? p : 0.f;

    if (!ok) sp = __int_as_float(0x7fc00000);   // NaN survives the reduction

    sp += __shfl_xor_sync(0xffffffffu, sp, 1);
    sp += __shfl_xor_sync(0xffffffffu, sp, 2);
    sn += __shfl_xor_sync(0xffffffffu, sn, 1);
    sn += __shfl_xor_sync(0xffffffffu, sn, 2);

    if (part == 0) {
        if (!isfinite(sp) || !isfinite(sn)) sp = __int_as_float(0x7fc00000);
        g_sp[c] = sp;
        g_sn[c] = sn;
        g_bf[c] = __ldg(b2 + c);
    }

    asm volatile("griddepcontrol.launch_dependents;");
}

// Exact per-element path for flagged channels (never taken on this dataset).
__device__ __noinline__ float bellows_exact(float xv, int c,
                                            const float* __restrict__ w1,
                                            const float* __restrict__ b1,
                                            const float* __restrict__ w2,
                                            float bias)
{
    float acc = 0.f;
    const float* w1r = w1 + (size_t)c * EE;
    const float* b1r = b1 + (size_t)c * EE;
    const float* w2r = w2 + (size_t)c * EE;
#pragma unroll 4
    for (int e = 0; e < EE; ++e) {
        float h = fmaxf(fmaf(xv, w1r[e], b1r[e]), 0.f);
        acc = fmaf(h, w2r[e], acc);
    }
    return fmaxf(acc + bias, 0.f);
}

__device__ __forceinline__ float bellows_fast(float xv, float sp, float sn, float bias)
{
    float s = (xv > 0.f) ? sp : sn;
    return fmaxf(fmaf(xv, s, bias), 0.f);
}

__global__ void __launch_bounds__(256)
apply_kernel(const float* __restrict__ x,
             const float* __restrict__ w1,
             const float* __restrict__ b1,
             const float* __restrict__ w2,
             float* __restrict__ out)
{
    int g = blockIdx.x * 256 + threadIdx.x;   // group of 4 channels
    if (g >= NG) return;
    int c  = g * 4;
    int b0 = blockIdx.y * RROWS;

    unsigned long long keep   = mk_keep();    // out + params: persist in carveout
    unsigned long long stream = mk_stream();  // x: stream, evict first

    const float* xp = x + (size_t)b0 * CC + c;
    float*       op = out + (size_t)b0 * CC + c;

    // x is independent of the precompute kernel: issue these loads BEFORE
    // griddepcontrol.wait so the predecessor's tail hides under them.
    float4 xv0 = ldg_pol(xp, stream);
    float4 xv1 = ldg_pol(xp + (size_t)1 * CC, stream);
    float4 xv2 = ldg_pol(xp + (size_t)2 * CC, stream);
    float4 xv3 = ldg_pol(xp + (size_t)3 * CC, stream);

    asm volatile("griddepcontrol.wait;" ::: "memory");

    float4 sp = ldg_pol(g_sp + c, keep);
    float4 sn = ldg_pol(g_sn + c, keep);
    float4 bf = ldg_pol(g_bf + c, keep);

    bool any_fb = (sp.x != sp.x) || (sp.y != sp.y) || (sp.z != sp.z) || (sp.w != sp.w);

    if (!any_fb) {
        float4 o;
        o.x = bellows_fast(xv0.x, sp.x, sn.x, bf.x);
        o.y = bellows_fast(xv0.y, sp.y, sn.y, bf.y);
        o.z = bellows_fast(xv0.z, sp.z, sn.z, bf.z);
        o.w = bellows_fast(xv0.w, sp.w, sn.w, bf.w);
        stg_pol(op, o, keep);
        o.x = bellows_fast(xv1.x, sp.x, sn.x, bf.x);
        o.y = bellows_fast(xv1.y, sp.y, sn.y, bf.y);
        o.z = bellows_fast(xv1.z, sp.z, sn.z, bf.z);
        o.w = bellows_fast(xv1.w, sp.w, sn.w, bf.w);
        stg_pol(op + (size_t)1 * CC, o, keep);
        o.x = bellows_fast(xv2.x, sp.x, sn.x, bf.x);
        o.y = bellows_fast(xv2.y, sp.y, sn.y, bf.y);
        o.z = bellows_fast(xv2.z, sp.z, sn.z, bf.z);
        o.w = bellows_fast(xv2.w, sp.w, sn.w, bf.w);
        stg_pol(op + (size_t)2 * CC, o, keep);
        o.x = bellows_fast(xv3.x, sp.x, sn.x, bf.x);
        o.y = bellows_fast(xv3.y, sp.y, sn.y, bf.y);
        o.z = bellows_fast(xv3.z, sp.z, sn.z, bf.z);
        o.w = bellows_fast(xv3.w, sp.w, sn.w, bf.w);
        stg_pol(op + (size_t)3 * CC, o, keep);
    } else {
        float4 xs[RROWS] = {xv0, xv1, xv2, xv3};
#pragma unroll
        for (int r = 0; r < RROWS; ++r) {
            float4 xv = xs[r];
            float4 o;
            o.x = (sp.x != sp.x) ? bellows_exact(xv.x, c + 0, w1, b1, w2, bf.x)
                                 : bellows_fast(xv.x, sp.x, sn.x, bf.x);
            o.y = (sp.y != sp.y) ? bellows_exact(xv.y, c + 1, w1, b1, w2, bf.y)
                                 : bellows_fast(xv.y, sp.y, sn.y, bf.y);
            o.z = (sp.z != sp.z) ? bellows_exact(xv.z, c + 2, w1, b1, w2, bf.z)
                                 : bellows_fast(xv.z, sp.z, sn.z, bf.z);
            o.w = (sp.w != sp.w) ? bellows_exact(xv.w, c + 3, w1, b1, w2, bf.w)
                                 : bellows_fast(xv.w, sp.w, sn.w, bf.w);
            stg_pol(op + (size_t)r * CC, o, keep);
        }
    }
}

extern "C" void kernel_launch(void* const* d_in, const int* in_sizes, int n_in,
                              void* d_out, int out_size)
{
    const float* x  = (const float*)d_in[0];   // (128, 40000)
    const float* w1 = (const float*)d_in[1];   // (40000, 16)
    const float* b1 = (const float*)d_in[2];   // (40000, 16)
    const float* w2 = (const float*)d_in[3];   // (40000, 16)
    const float* b2 = (const float*)d_in[4];   // (40000,)
    float* out = (float*)d_out;                // (128, 2, 20000) == (128, 40000)

    precompute_kernel<<<(CC * 4 + 255) / 256, 256>>>(w1, b1, w2, b2);

    // apply: Programmatic Stream Serialization so it begins while precompute
    // drains; griddepcontrol.wait provides the param-visibility ordering.
    cudaLaunchConfig_t cfg = {};
    cfg.gridDim  = dim3((NG + 255) / 256, BB / RROWS);   // (40, 32) = 1280 blocks
    cfg.blockDim = dim3(256, 1, 1);
    cfg.dynamicSmemBytes = 0;
    cfg.stream = 0;   // same (capture) stream as the precompute launch

    cudaLaunchAttribute attrs[1];
    attrs[0].id = cudaLaunchAttributeProgrammaticStreamSerialization;
    attrs[0].val.programmaticStreamSerializationAllowed = 1;
    cfg.attrs = attrs;
    cfg.numAttrs = 1;

    cudaLaunchKernelEx(&cfg, apply_kernel, x, w1, b1, w2, out);
}